// round 17
// baseline (speedup 1.0000x reference)
#include <cuda_runtime.h>
#include <cuda_pipeline.h>
#include <cuda_bf16.h>
#include <mma.h>
#include <math.h>

using namespace nvcuda;

#define BATCH  64
#define SEQ    512
#define INSZ   1024
#define HID    1024
#define G4     4096
#define BSH    (BATCH * SEQ * HID)
#define CTAS   128
#define THREADS 256
#define HB     8           // hidden units per CTA
#define NC     32          // gate-columns per CTA (4 gates x 8)
#define SWP    34          // sW row pitch (floats, EVEN — wmma ldm)
#define ACP    36          // sAcc row pitch (floats, EVEN — wmma acc ldm; 33 was the R15 bug)
#define TD     16          // dense warmup steps
#define XAP    40          // gemm bf16 A pitch
#define XBP    136         // gemm bf16 B pitch

// Scratch (device globals)
__device__ float g_Gx[(size_t)SEQ * BATCH * G4];   // [t][b][4096]
__device__ float g_hbuf[2][BATCH * HID];           // ping-pong hmax (warmup only)
__device__ unsigned g_bar[SEQ];                    // arrival counters
__device__ unsigned g_rel[SEQ];                    // release flags (separate lines)
__device__ float2 g_blist[3][BATCH][HID];          // triple-buffered record lists
__device__ int    g_lcnt[3][BATCH];                // list counters
// split-bf16 planes
__device__ __nv_bfloat16 g_xh[(size_t)BATCH * SEQ * INSZ];
__device__ __nv_bfloat16 g_xl[(size_t)BATCH * SEQ * INSZ];
__device__ __nv_bfloat16 g_wh[(size_t)INSZ * G4];
__device__ __nv_bfloat16 g_wl[(size_t)INSZ * G4];

// ---------------------------------------------------------------------------
// Phase 0: split x and W(x-part) into bf16 hi/lo planes; re-init state.
// ---------------------------------------------------------------------------
__global__ __launch_bounds__(256) void k_cvt(
    const float* __restrict__ x,
    const float* __restrict__ Wf, const float* __restrict__ Wi,
    const float* __restrict__ Wc, const float* __restrict__ Wo)
{
    const int tid = threadIdx.x;
    if (blockIdx.x == 0) {
        for (int i = tid; i < SEQ; i += 256) { g_bar[i] = 0u; g_rel[i] = 0u; }
        for (int i = tid; i < 3 * BATCH; i += 256) (&g_lcnt[0][0])[i] = 0;
    }
    const size_t NX = (size_t)BATCH * SEQ * INSZ;
    const size_t NW = (size_t)INSZ * G4;
    const size_t stride = (size_t)gridDim.x * 256;
    for (size_t i = blockIdx.x * 256ull + tid; i < NX; i += stride) {
        float v = x[i];
        __nv_bfloat16 h = __float2bfloat16(v);
        g_xh[i] = h;
        g_xl[i] = __float2bfloat16(v - __bfloat162float(h));
    }
    for (size_t i = blockIdx.x * 256ull + tid; i < NW; i += stride) {
        int k = (int)(i >> 12);
        int col = (int)(i & 4095);
        int g = col >> 10, c = col & 1023;
        const float* W = (g == 0) ? Wf : (g == 1) ? Wi : (g == 2) ? Wc : Wo;
        float v = W[(size_t)(1024 + k) * 1024 + c];
        __nv_bfloat16 h = __float2bfloat16(v);
        g_wh[i] = h;
        g_wl[i] = __float2bfloat16(v - __bfloat162float(h));
    }
}

// ---------------------------------------------------------------------------
// Phase 1: Gx = X @ Wx via split-bf16 (hi+lo), fp32 accum. (R12 — known good)
// 128x128 tile, BK=32, 2-stage cp.async; products hh + hl + lh.
// ---------------------------------------------------------------------------
__global__ __launch_bounds__(256) void k_gemm_x()
{
    extern __shared__ __nv_bfloat16 bsm[];
    __nv_bfloat16 (*sAh)[128][XAP] = (__nv_bfloat16(*)[128][XAP])bsm;
    __nv_bfloat16 (*sAl)[128][XAP] = (__nv_bfloat16(*)[128][XAP])(bsm + 2 * 128 * XAP);
    __nv_bfloat16 (*sBh)[32][XBP]  = (__nv_bfloat16(*)[32][XBP]) (bsm + 4 * 128 * XAP);
    __nv_bfloat16 (*sBl)[32][XBP]  = (__nv_bfloat16(*)[32][XBP]) (bsm + 4 * 128 * XAP + 2 * 32 * XBP);

    const int tid  = threadIdx.x;
    const int bn = blockIdx.x;                 // 0..31
    const int bm = blockIdx.y;                 // 0..255
    const int c0 = bn * 128;

    const int warp = tid >> 5;
    const int wm   = warp & 3;
    const int wn   = warp >> 2;

    auto issue = [&](int stage, int kc) {
#pragma unroll
        for (int l = 0; l < 2; l++) {
            int f = tid + l * 256;
            int r = f >> 2, c = f & 3;
            size_t src = (size_t)(bm * 128 + r) * 1024 + kc * 32 + c * 8;
            __pipeline_memcpy_async(&sAh[stage][r][c * 8], g_xh + src, 16);
            __pipeline_memcpy_async(&sAl[stage][r][c * 8], g_xl + src, 16);
        }
#pragma unroll
        for (int l = 0; l < 2; l++) {
            int f = tid + l * 256;
            int kr = f >> 4, c = f & 15;
            size_t src = (size_t)(kc * 32 + kr) * G4 + c0 + c * 8;
            __pipeline_memcpy_async(&sBh[stage][kr][c * 8], g_wh + src, 16);
            __pipeline_memcpy_async(&sBl[stage][kr][c * 8], g_wl + src, 16);
        }
        __pipeline_commit();
    };

    wmma::fragment<wmma::accumulator, 16, 16, 16, float> acc[2][4];
#pragma unroll
    for (int i = 0; i < 2; i++)
#pragma unroll
        for (int j = 0; j < 4; j++) wmma::fill_fragment(acc[i][j], 0.f);

    issue(0, 0);
    for (int kc = 0; kc < 32; ++kc) {
        if (kc + 1 < 32) { issue((kc + 1) & 1, kc + 1); __pipeline_wait_prior(1); }
        else             { __pipeline_wait_prior(0); }
        __syncthreads();

        const int st = kc & 1;
#pragma unroll
        for (int kk = 0; kk < 2; ++kk) {
            const int k0 = kk * 16;
            wmma::fragment<wmma::matrix_a, 16, 16, 16, __nv_bfloat16, wmma::row_major> ah[2], al[2];
            wmma::fragment<wmma::matrix_b, 16, 16, 16, __nv_bfloat16, wmma::row_major> bh[4], bl[4];
#pragma unroll
            for (int i = 0; i < 2; i++) {
                wmma::load_matrix_sync(ah[i], &sAh[st][wm * 32 + i * 16][k0], XAP);
                wmma::load_matrix_sync(al[i], &sAl[st][wm * 32 + i * 16][k0], XAP);
            }
#pragma unroll
            for (int j = 0; j < 4; j++) {
                wmma::load_matrix_sync(bh[j], &sBh[st][k0][wn * 64 + j * 16], XBP);
                wmma::load_matrix_sync(bl[j], &sBl[st][k0][wn * 64 + j * 16], XBP);
            }
#pragma unroll
            for (int i = 0; i < 2; i++)
#pragma unroll
                for (int j = 0; j < 4; j++) {
                    wmma::mma_sync(acc[i][j], ah[i], bh[j], acc[i][j]);
                    wmma::mma_sync(acc[i][j], ah[i], bl[j], acc[i][j]);
                    wmma::mma_sync(acc[i][j], al[i], bh[j], acc[i][j]);
                }
        }
        __syncthreads();
    }

    // Store with row remap m = b*512 + t -> out row t*64 + b (stride folded in ldm)
#pragma unroll
    for (int i = 0; i < 2; i++) {
        int m0 = bm * 128 + wm * 32 + i * 16;
        int bidx = m0 >> 9;
        int t0 = m0 & 511;
        float* rowbase = g_Gx + (size_t)(t0 * 64 + bidx) * G4 + c0 + wn * 64;
#pragma unroll
        for (int j = 0; j < 4; j++)
            wmma::store_matrix_sync(rowbase + j * 16, acc[i][j],
                                    (unsigned)(64 * G4), wmma::mem_row_major);
    }
}

// ---------------------------------------------------------------------------
// Phase 2: persistent kernel. Dense tf32 warmup (t<TD) writes per-warp full-K
// m16n16 tiles straight into sAcc (even ldm); then sparse rank-1 cummax-record
// updates with single-sync batched staging. R11-tested barrier.
// ---------------------------------------------------------------------------
__device__ __forceinline__ float sigf(float v) {
    return __fdividef(1.f, 1.f + __expf(-v));
}
__device__ __forceinline__ float tanhfast(float v) {
    float ex = __expf(2.f * v);
    return 1.f - __fdividef(2.f, ex + 1.f);
}

__global__ __launch_bounds__(THREADS, 1) void k_lstm(
    const float* __restrict__ Wf, const float* __restrict__ Wi,
    const float* __restrict__ Wc, const float* __restrict__ Wo,
    const float* __restrict__ bfv, const float* __restrict__ biv,
    const float* __restrict__ bcv, const float* __restrict__ bov,
    float* __restrict__ out)
{
    extern __shared__ float smem[];
    float*  sW   = smem;                           // [1024][SWP] fp32 weights
    float*  sAcc = smem + 1024 * SWP;              // [64][ACP] accumulator
    float2* sStg = (float2*)(sAcc + 64 * ACP);     // [8 warps][8 b][32] staging

    __shared__ float sBias[NC];

    const int tid  = threadIdx.x;
    const int warp = tid >> 5;
    const int lane = tid & 31;
    const int h0   = blockIdx.x * HB;

    for (int k = tid; k < 1024; k += THREADS) {
#pragma unroll
        for (int g = 0; g < 4; g++) {
            const float* W = (g == 0) ? Wf : (g == 1) ? Wi : (g == 2) ? Wc : Wo;
            float4 v0 = *reinterpret_cast<const float4*>(W + (size_t)k * 1024 + h0);
            float4 v1 = *reinterpret_cast<const float4*>(W + (size_t)k * 1024 + h0 + 4);
            float* d = &sW[k * SWP + g * 8];
            d[0] = v0.x; d[1] = v0.y; d[2] = v0.z; d[3] = v0.w;
            d[4] = v1.x; d[5] = v1.y; d[6] = v1.z; d[7] = v1.w;
        }
    }
    for (int i = tid; i < 64 * ACP; i += THREADS) sAcc[i] = 0.f;
    if (tid < NC) {
        int g = tid >> 3, hh = tid & 7;
        const float* bv = (g == 0) ? bfv : (g == 1) ? biv : (g == 2) ? bcv : bov;
        sBias[tid] = bv[h0 + hh];
    }
    __syncthreads();

    float creg[2] = {0.f, 0.f};
    float hreg[2] = {0.f, 0.f};

    float gx[2][4];
#pragma unroll
    for (int l = 0; l < 2; l++) {
        int e = tid + l * THREADS;
        int b = e >> 3, hh = e & 7;
        const float* gp = g_Gx + (size_t)b * G4 + h0 + hh;
#pragma unroll
        for (int g = 0; g < 4; g++) gx[l][g] = __ldcg(gp + g * 1024);
    }

    for (int t = 0; t < SEQ; ++t) {
        if (blockIdx.x < BATCH && tid == 0)
            atomicExch(&g_lcnt[(t + 1) % 3][blockIdx.x], 0);

        const bool dense = (t < TD);

        if (t > 0) {
            if (dense) {
                // warp w: full-K m16n16 tile -> sAcc rows (w&3)*16, cols (w>>2)*16
                const float* __restrict__ hin = g_hbuf[(t + 1) & 1];
                const int r0 = (warp & 3) * 16;
                const int c0 = (warp >> 2) * 16;
                wmma::fragment<wmma::accumulator, 16, 16, 8, float> acc;
                wmma::fill_fragment(acc, 0.f);
#pragma unroll 4
                for (int k = 0; k < 1024; k += 8) {
                    wmma::fragment<wmma::matrix_a, 16, 16, 8, wmma::precision::tf32, wmma::row_major> af;
                    wmma::fragment<wmma::matrix_b, 16, 16, 8, wmma::precision::tf32, wmma::row_major> bf;
                    wmma::load_matrix_sync(af, hin + (size_t)r0 * 1024 + k, 1024);
                    wmma::load_matrix_sync(bf, &sW[k * SWP + c0], SWP);
#pragma unroll
                    for (int e = 0; e < af.num_elements; e++)
                        af.x[e] = wmma::__float_to_tf32(af.x[e]);
#pragma unroll
                    for (int e = 0; e < bf.num_elements; e++)
                        bf.x[e] = wmma::__float_to_tf32(bf.x[e]);
                    wmma::mma_sync(acc, af, bf, acc);
                }
                wmma::store_matrix_sync(&sAcc[r0 * ACP + c0], acc, ACP, wmma::mem_row_major);
                __syncthreads();
            } else {
                // ---- sparse apply: single-sync batched staging ----
                const int ph = (t + 2) % 3;              // == (t-1) % 3
                const int b0 = warp << 3;
                int myc = (lane < 8) ? __ldcg(&g_lcnt[ph][b0 + lane]) : 0;
                int n[8];
#pragma unroll
                for (int bb = 0; bb < 8; bb++)
                    n[bb] = __shfl_sync(0xffffffffu, myc, bb);

                float acc8[8];
#pragma unroll
                for (int bb = 0; bb < 8; bb++)
                    acc8[bb] = sAcc[(b0 + bb) * ACP + lane];

                // first 32-entry batch for all 8 b's, fetched in parallel
                float2 pre[8];
#pragma unroll
                for (int bb = 0; bb < 8; bb++)
                    pre[bb] = (lane < n[bb])
                        ? __ldcg(&g_blist[ph][b0 + bb][lane])
                        : make_float2(0.f, 0.f);

                float2* stg = &sStg[warp * 256];         // 8 b x 32 slots
#pragma unroll
                for (int bb = 0; bb < 8; bb++)
                    stg[bb * 32 + lane] = pre[bb];
                __syncwarp();

#pragma unroll
                for (int bb = 0; bb < 8; bb++) {
                    int nb = min(n[bb], 32);
                    for (int j = 0; j < nb; ++j) {
                        float2 E = stg[bb * 32 + j];     // LDS broadcast
                        acc8[bb] += E.y * sW[__float_as_int(E.x) * SWP + lane];
                    }
                }

                // rare tails (n > 32; only shortly after warmup)
#pragma unroll
                for (int bb = 0; bb < 8; bb++) {
                    if (n[bb] > 32) {
                        for (int base = 32; base < n[bb]; base += 32) {
                            float2 cur = (lane < n[bb] - base)
                                ? __ldcg(&g_blist[ph][b0 + bb][base + lane])
                                : make_float2(0.f, 0.f);
                            __syncwarp();
                            stg[bb * 32 + lane] = cur;
                            __syncwarp();
                            int cnt = min(32, n[bb] - base);
                            for (int j = 0; j < cnt; ++j) {
                                float2 E = stg[bb * 32 + j];
                                acc8[bb] += E.y * sW[__float_as_int(E.x) * SWP + lane];
                            }
                        }
                    }
                }
#pragma unroll
                for (int bb = 0; bb < 8; bb++)
                    sAcc[(b0 + bb) * ACP + lane] = acc8[bb];
                __syncthreads();
            }
        }

        // ---- elementwise: gates, state, cummax, record emission ----
        float* __restrict__ hnew = g_hbuf[t & 1];
        float outv[2];
        bool emitted = false;
#pragma unroll
        for (int l = 0; l < 2; l++) {
            int e  = tid + l * THREADS;
            int b  = e >> 3, hh = e & 7;
            int h  = h0 + hh;

            float s0 = sAcc[b * ACP + hh];
            float s1 = sAcc[b * ACP + 8 + hh];
            float s2 = sAcc[b * ACP + 16 + hh];
            float s3 = sAcc[b * ACP + 24 + hh];

            float gf = s0 + gx[l][0] + sBias[hh];
            float gi = s1 + gx[l][1] + sBias[8 + hh];
            float gc = s2 + gx[l][2] + sBias[16 + hh];
            float go = s3 + gx[l][3] + sBias[24 + hh];

            float Cn = sigf(gf) * creg[l] + sigf(gi) * tanhfast(gc);
            creg[l] = Cn;
            float hv = sigf(go) * tanhfast(Cn);
            outv[l] = hv;

            if (t >= TD - 1 && t < SEQ - 1 && hv > hreg[l]) {
                float dlt = hv - hreg[l];
                int pos = atomicAdd(&g_lcnt[t % 3][b], 1);
                g_blist[t % 3][b][pos] = make_float2(__int_as_float(h), dlt);
                emitted = true;
            }
            float hm = (t == 0) ? hv : fmaxf(hreg[l], hv);
            hreg[l] = hm;

            if (t < TD - 1) hnew[b * HID + h] = hm;

            if (t == SEQ - 1) {
                out[(size_t)b * SEQ * HID + (size_t)t * HID + h] = hv;
                out[(size_t)BSH + b * HID + h] = hm;                     // h_fin
                out[(size_t)BSH + BATCH * HID + b * HID + h] = Cn;       // C_fin
            }
        }

        if (t < SEQ - 1) {
            if (dense || emitted) __threadfence();   // release payload stores
            __syncthreads();
            unsigned arr = 0;
            if (tid == 0) arr = atomicAdd(&g_bar[t], 1u) + 1;

            // ---- work hidden under the barrier ----
#pragma unroll
            for (int l = 0; l < 2; l++) {
                int e = tid + l * THREADS;
                int b = e >> 3, hh = e & 7;
                out[(size_t)b * SEQ * HID + (size_t)t * HID + h0 + hh] = outv[l];
            }
#pragma unroll
            for (int l = 0; l < 2; l++) {
                int e = tid + l * THREADS;
                int b = e >> 3, hh = e & 7;
                const float* gp = g_Gx + (size_t)((t + 1) * 64 + b) * G4 + h0 + hh;
#pragma unroll
                for (int g = 0; g < 4; g++) gx[l][g] = __ldcg(gp + g * 1024);
            }

            if (tid == 0) {
                if (arr == CTAS) {
                    __stcg(&g_rel[t], 1u);           // release flag (own line)
                } else {
                    volatile unsigned* p = &g_rel[t];
                    while (*p == 0u) { }             // poll read-only line
                }
                if (t + 1 < TD) __threadfence();     // L1 inval for dense hbuf reads
            }
            __syncthreads();
        }
    }
}

extern "C" void kernel_launch(void* const* d_in, const int* in_sizes, int n_in,
                              void* d_out, int out_size) {
    const float* x  = (const float*)d_in[0];
    const float* Wf = (const float*)d_in[1];
    const float* bf = (const float*)d_in[2];
    const float* Wi = (const float*)d_in[3];
    const float* bi = (const float*)d_in[4];
    const float* Wc = (const float*)d_in[5];
    const float* bc = (const float*)d_in[6];
    const float* Wo = (const float*)d_in[7];
    const float* bo = (const float*)d_in[8];
    float* out = (float*)d_out;

    static const size_t SMEM_L = (1024 * SWP + 64 * ACP) * sizeof(float)
                                 + 8 * 256 * sizeof(float2);              // 164,864 B
    static const size_t SMEM_G = (4 * 128 * XAP + 4 * 32 * XBP) * sizeof(__nv_bfloat16);
    cudaFuncSetAttribute(k_lstm,   cudaFuncAttributeMaxDynamicSharedMemorySize, (int)SMEM_L);
    cudaFuncSetAttribute(k_gemm_x, cudaFuncAttributeMaxDynamicSharedMemorySize, (int)SMEM_G);

    k_cvt<<<8192, 256>>>(x, Wf, Wi, Wc, Wo);
    k_gemm_x<<<dim3(32, 256), 256, SMEM_G>>>();
    k_lstm<<<CTAS, THREADS, SMEM_L>>>(Wf, Wi, Wc, Wo, bf, bi, bc, bo, out);
}